// round 6
// baseline (speedup 1.0000x reference)
#include <cuda_runtime.h>
#include <cstdint>
#include <math.h>

// ---------------- problem dims ----------------
#define NTOK 8192
#define DIMD 1024
#define HID  4096
#define NEXP 8
#define NA   (NTOK*2)          // total assignments (top-2)

// ---------------- GEMM tiling ----------------
#define BM 128
#define BN 128
#define BK 32
#define NS 3                   // cp.async pipeline stages
#define MAXT 144               // >= worst-case sum of ceil(cnt_e/128)
#define STAGEB (BM*BK*4)       // 16 KB per operand tile
#define STAGE_BYTES (2*STAGEB) // 32 KB per stage
#define DYN_SMEM (NS*STAGE_BYTES)   // 96 KB (also holds 128x132 f32 epilogue staging)
#define EPI_STRIDE 132

// ---------------- device scratch ----------------
__device__ float g_x  [(size_t)NTOK*DIMD];        // tf32-rounded x  [tok][D]
__device__ float g_w1t[(size_t)NEXP*DIMD*HID];    // tf32-rounded W1^T  [e][H][D]
__device__ float g_w2t[(size_t)NEXP*HID*DIMD];    // tf32-rounded W2^T  [e][D][H]
__device__ float g_h  [(size_t)(NA+BM)*HID];      // hidden activations [assign][H]
__device__ int   g_top_idx[NTOK*2];
__device__ float g_top_gate[NTOK*2];
__device__ int   g_count[NEXP];
__device__ int   g_offset[NEXP+1];
__device__ int   g_cursor[NEXP];
__device__ float g_importance[NEXP];
__device__ int   g_tok[NA];
__device__ float g_gate[NA];
__device__ int   g_tile_e[MAXT];
__device__ int   g_tile_m[MAXT];
__device__ int   g_ntiles;

// ---------------- PTX helpers ----------------
__device__ __forceinline__ uint32_t smem_u32(const void* p) {
    uint32_t a;
    asm("{ .reg .u64 t; cvta.to.shared.u64 t, %1; cvt.u32.u64 %0, t; }" : "=r"(a) : "l"(p));
    return a;
}
__device__ __forceinline__ float rnd_tf32(float f) {
    uint32_t u; asm("cvt.rna.tf32.f32 %0, %1;" : "=r"(u) : "f"(f));
    return __uint_as_float(u);
}
__device__ __forceinline__ void cpa16(uint32_t smem_dst, const void* gsrc) {
    asm volatile("cp.async.cg.shared.global [%0], [%1], 16;\n" :: "r"(smem_dst), "l"(gsrc));
}
#define CP_COMMIT() asm volatile("cp.async.commit_group;\n" ::: "memory")

__device__ __forceinline__ void ldsm4(uint32_t* r, uint32_t addr) {
    asm volatile("ldmatrix.sync.aligned.m8n8.x4.shared.b16 {%0,%1,%2,%3}, [%4];"
                 : "=r"(r[0]), "=r"(r[1]), "=r"(r[2]), "=r"(r[3]) : "r"(addr));
}
__device__ __forceinline__ void mma_tf32(float* c, const uint32_t* a, const uint32_t* b) {
    asm volatile(
        "mma.sync.aligned.m16n8k8.row.col.f32.tf32.tf32.f32 "
        "{%0,%1,%2,%3}, {%4,%5,%6,%7}, {%8,%9}, {%0,%1,%2,%3};\n"
        : "+f"(c[0]), "+f"(c[1]), "+f"(c[2]), "+f"(c[3])
        : "r"(a[0]), "r"(a[1]), "r"(a[2]), "r"(a[3]), "r"(b[0]), "r"(b[1]));
}
// SW128 swizzle inside a [rows][128B] tile: 16B chunk index XOR low row bits
__device__ __forceinline__ uint32_t swz(uint32_t base, int row, int ch) {
    return base + (uint32_t)row * 128u + ((uint32_t)((ch ^ (row & 7)) & 7) << 4);
}

// ---------------- init: zero output + counters + round x ----------------
__global__ void init_kernel(float* __restrict__ out, const float* __restrict__ x) {
    size_t i = (size_t)blockIdx.x * blockDim.x + threadIdx.x;
    size_t stride = (size_t)gridDim.x * blockDim.x;
    size_t n4 = (size_t)NTOK * DIMD / 4;
    float4 z = make_float4(0.f, 0.f, 0.f, 0.f);
    const float4* sx = (const float4*)x;
    float4* dx = (float4*)g_x;
    for (size_t j = i; j < n4; j += stride) {
        reinterpret_cast<float4*>(out)[j] = z;
        float4 v = sx[j];
        dx[j] = make_float4(rnd_tf32(v.x), rnd_tf32(v.y), rnd_tf32(v.z), rnd_tf32(v.w));
    }
    if (blockIdx.x == 0 && threadIdx.x < NEXP) {
        g_count[threadIdx.x] = 0;
        g_importance[threadIdx.x] = 0.f;
    }
}

// ---------------- transpose + tf32-round weights ----------------
// z<8:  W1[e] [D][H] -> g_w1t[e] [H][D]
// z>=8: W2[e] [H][D] -> g_w2t[e] [D][H]
__global__ void prep_kernel(const float* __restrict__ W1, const float* __restrict__ W2) {
    const int z = blockIdx.z;
    const float* src; float* dst; int R, C;
    if (z < NEXP) { src = W1 + (size_t)z*DIMD*HID;        dst = g_w1t + (size_t)z*DIMD*HID;        R = DIMD; C = HID; }
    else          { src = W2 + (size_t)(z-NEXP)*HID*DIMD; dst = g_w2t + (size_t)(z-NEXP)*HID*DIMD; R = HID;  C = DIMD; }
    const int j0 = blockIdx.x * 32, i0 = blockIdx.y * 32;
    if (j0 >= C || i0 >= R) return;
    __shared__ float t[32][33];
    const int tx = threadIdx.x & 31, ty = threadIdx.x >> 5;   // 256 threads: 32x8
#pragma unroll
    for (int k = 0; k < 4; k++)
        t[ty + k*8][tx] = rnd_tf32(src[(size_t)(i0 + ty + k*8) * C + j0 + tx]);
    __syncthreads();
#pragma unroll
    for (int k = 0; k < 4; k++)
        dst[(size_t)(j0 + ty + k*8) * R + i0 + tx] = t[tx][ty + k*8];
}

// ---------------- gating: one block per token ----------------
__global__ void gate_kernel(const float* __restrict__ x,
                            const float* __restrict__ Wg,
                            const float* __restrict__ bg) {
    const int t = blockIdx.x;
    const int tid = threadIdx.x;     // 128 threads
    const float* xr = x + (size_t)t * DIMD;

    float acc[NEXP];
#pragma unroll
    for (int e = 0; e < NEXP; e++) acc[e] = 0.f;
    for (int d = tid; d < DIMD; d += 128) {
        float xv = xr[d];
        const float* w = Wg + d * NEXP;
#pragma unroll
        for (int e = 0; e < NEXP; e++) acc[e] += xv * w[e];
    }
#pragma unroll
    for (int e = 0; e < NEXP; e++) {
#pragma unroll
        for (int o = 16; o > 0; o >>= 1)
            acc[e] += __shfl_down_sync(0xffffffffu, acc[e], o);
    }
    __shared__ float part[4][NEXP];
    if ((tid & 31) == 0) {
#pragma unroll
        for (int e = 0; e < NEXP; e++) part[tid >> 5][e] = acc[e];
    }
    __syncthreads();
    if (tid == 0) {
        float lg[NEXP];
#pragma unroll
        for (int e = 0; e < NEXP; e++)
            lg[e] = part[0][e] + part[1][e] + part[2][e] + part[3][e] + bg[e];
        float mx = lg[0];
        for (int e = 1; e < NEXP; e++) mx = fmaxf(mx, lg[e]);
        float s = 0.f, p[NEXP];
#pragma unroll
        for (int e = 0; e < NEXP; e++) { p[e] = expf(lg[e] - mx); s += p[e]; }
        float inv = 1.f / s;
#pragma unroll
        for (int e = 0; e < NEXP; e++) atomicAdd(&g_importance[e], p[e] * inv);
        int i1 = 0;
        for (int e = 1; e < NEXP; e++) if (lg[e] > lg[i1]) i1 = e;
        int i2 = -1;
        for (int e = 0; e < NEXP; e++)
            if (e != i1 && (i2 < 0 || lg[e] > lg[i2])) i2 = e;
        float e2 = expf(lg[i2] - lg[i1]);
        float g1 = 1.f / (1.f + e2);
        float g2 = e2 * g1;
        g_top_idx[2*t] = i1;  g_top_idx[2*t+1] = i2;
        g_top_gate[2*t] = g1; g_top_gate[2*t+1] = g2;
        atomicAdd(&g_count[i1], 1);
        atomicAdd(&g_count[i2], 1);
    }
}

// ---------------- plan + scatter ----------------
__global__ void plan_kernel() {
    if (threadIdx.x == 0 && blockIdx.x == 0) {
        int off = 0, nt = 0;
        for (int e = 0; e < NEXP; e++) {
            g_offset[e] = off;
            g_cursor[e] = 0;
            int c = g_count[e];
            off += c;
            int mt = (c + BM - 1) / BM;
            for (int i = 0; i < mt; i++) { g_tile_e[nt] = e; g_tile_m[nt] = i*BM; nt++; }
        }
        g_offset[NEXP] = off;
        g_ntiles = nt;
    }
}
__global__ void scatter_kernel() {
    int t = blockIdx.x * blockDim.x + threadIdx.x;
    if (t < NTOK) {
#pragma unroll
        for (int k = 0; k < 2; k++) {
            int e = g_top_idx[2*t+k];
            int p = atomicAdd(&g_cursor[e], 1);
            int s = g_offset[e] + p;
            g_tok[s] = t;
            g_gate[s] = g_top_gate[2*t+k];
        }
    }
}

// ---------------- grouped GEMM: legacy tf32 mma.sync + ldmatrix ----------------
// FIRST:  h = rnd(relu(gather(g_x) @ W1[e] + b1[e]))   A:[128][1024]  B^T:[H][D]
// !FIRST: out[tok] += gate*(g_h @ W2[e] + b2[e])       A:[128][4096]  B^T:[D][H]
template<bool FIRST>
__global__ void __launch_bounds__(256, 1)
moe_gemm(const float* __restrict__ b1, const float* __restrict__ b2,
         float* __restrict__ out)
{
    const int tix = blockIdx.y;
    if (tix >= g_ntiles) return;
    const int e      = g_tile_e[tix];
    const int mstart = g_tile_m[tix];
    const int off    = g_offset[e];
    const int cnt    = g_count[e];
    const int n0     = blockIdx.x * BN;
    const int K      = FIRST ? DIMD : HID;
    const int ldk    = FIRST ? DIMD : HID;   // B^T row length (k-contig)
    const int KIT    = K / BK;
    const float* Bt  = FIRST ? (g_w1t + (size_t)e*DIMD*HID)
                             : (g_w2t + (size_t)e*HID*DIMD);

    extern __shared__ __align__(16) char dsm[];
    const uint32_t sbase = smem_u32(dsm);

    __shared__ int   s_tok[BM];
    __shared__ float s_gate[BM];

    const int tid  = threadIdx.x;
    const int wid  = tid >> 5, lane = tid & 31;
    const int wm   = wid >> 2, wn = wid & 3;      // 2x4 warp grid, warp tile 64m x 32n

    for (int r = tid; r < BM; r += 256) {
        int gr = mstart + r;
        bool v = gr < cnt;
        s_tok[r]  = v ? g_tok[off+gr]  : 0;
        s_gate[r] = v ? g_gate[off+gr] : 0.f;
    }
    __syncthreads();

    float acc[4][4][4];
#pragma unroll
    for (int i = 0; i < 4; i++)
#pragma unroll
        for (int j = 0; j < 4; j++)
#pragma unroll
            for (int q = 0; q < 4; q++) acc[i][j][q] = 0.f;

    // stage loader: A tile [128 rows][32 k] SW128, B tile [128 n][32 k] SW128
    auto load_stage = [&](int buf, int k0) {
        uint32_t abuf = sbase + (uint32_t)buf * STAGE_BYTES;
        uint32_t bbuf = abuf + STAGEB;
#pragma unroll
        for (int i = 0; i < 4; i++) {
            int idx = tid + i * 256;          // 0..1023
            int row = idx >> 3, ch = idx & 7;
            const float* asrc;
            if (FIRST) asrc = g_x + (size_t)s_tok[row] * DIMD + k0 + ch * 4;
            else       asrc = g_h + (size_t)(off + mstart + row) * HID + k0 + ch * 4;
            cpa16(swz(abuf, row, ch), asrc);
        }
#pragma unroll
        for (int i = 0; i < 4; i++) {
            int idx = tid + i * 256;
            int row = idx >> 3, ch = idx & 7;   // row = n index
            cpa16(swz(bbuf, row, ch),
                  Bt + (size_t)(n0 + row) * ldk + k0 + ch * 4);
        }
    };

    load_stage(0, 0);       CP_COMMIT();
    load_stage(1, BK);      CP_COMMIT();

    for (int kt = 0; kt < KIT; kt++) {
        const int buf = kt % NS;
        if (kt == KIT - 1) asm volatile("cp.async.wait_group 0;" ::: "memory");
        else               asm volatile("cp.async.wait_group 1;" ::: "memory");
        __syncthreads();

        if (kt + 2 < KIT) {                   // prefetch stage kt+2
            load_stage((kt + 2) % NS, (kt + 2) * BK);
            CP_COMMIT();
        }

        const uint32_t abuf = sbase + (uint32_t)buf * STAGE_BYTES;
        const uint32_t bbuf = abuf + STAGEB;
#pragma unroll
        for (int ks = 0; ks < 4; ks++) {
            uint32_t a[4][4], b[2][4];
#pragma unroll
            for (int mi = 0; mi < 4; mi++) {
                int row = wm * 64 + mi * 16 + (lane & 7) + ((lane >> 3) & 1) * 8;
                int ch  = ks * 2 + (lane >> 4);
                ldsm4(a[mi], swz(abuf, row, ch));
            }
#pragma unroll
            for (int nip = 0; nip < 2; nip++) {
                int row = wn * 32 + nip * 16 + (lane & 7) + ((lane >> 4) << 3);
                int ch  = ks * 2 + ((lane >> 3) & 1);
                ldsm4(b[nip], swz(bbuf, row, ch));
            }
#pragma unroll
            for (int mi = 0; mi < 4; mi++)
#pragma unroll
                for (int ni = 0; ni < 4; ni++)
                    mma_tf32(acc[mi][ni], a[mi], &b[ni >> 1][(ni & 1) * 2]);
        }
        __syncthreads();
    }

    // ---- epilogue: stage accs to smem (stride 132), then coalesced flush ----
    float* st = (float*)dsm;
#pragma unroll
    for (int mi = 0; mi < 4; mi++) {
#pragma unroll
        for (int ni = 0; ni < 4; ni++) {
            int r = wm * 64 + mi * 16 + (lane >> 2);
            int c = wn * 32 + ni * 8 + ((lane & 3) << 1);
            *reinterpret_cast<float2*>(&st[r * EPI_STRIDE + c]) =
                make_float2(acc[mi][ni][0], acc[mi][ni][1]);
            *reinterpret_cast<float2*>(&st[(r + 8) * EPI_STRIDE + c]) =
                make_float2(acc[mi][ni][2], acc[mi][ni][3]);
        }
    }
    __syncthreads();

    {
        const int row  = tid >> 1;
        const int half = (tid & 1) * 64;
        if (mstart + row < cnt) {
            const float* bias = (FIRST ? b1 + (size_t)e * HID
                                       : b2 + (size_t)e * DIMD) + n0 + half;
            if (FIRST) {
                float* dst = g_h + (size_t)(off + mstart + row) * HID + n0 + half;
#pragma unroll
                for (int j = 0; j < 16; j++) {
                    float4 v = *reinterpret_cast<float4*>(&st[row * EPI_STRIDE + half + j * 4]);
                    float4 bb = *reinterpret_cast<const float4*>(bias + j * 4);
                    v.x = rnd_tf32(fmaxf(v.x + bb.x, 0.f));
                    v.y = rnd_tf32(fmaxf(v.y + bb.y, 0.f));
                    v.z = rnd_tf32(fmaxf(v.z + bb.z, 0.f));
                    v.w = rnd_tf32(fmaxf(v.w + bb.w, 0.f));
                    *reinterpret_cast<float4*>(dst + j * 4) = v;
                }
            } else {
                const float g = s_gate[row];
                float* dst = out + (size_t)s_tok[row] * DIMD + n0 + half;
#pragma unroll
                for (int j = 0; j < 16; j++) {
                    float4 v = *reinterpret_cast<float4*>(&st[row * EPI_STRIDE + half + j * 4]);
                    float4 bb = *reinterpret_cast<const float4*>(bias + j * 4);
                    atomicAdd(dst + j * 4 + 0, (v.x + bb.x) * g);
                    atomicAdd(dst + j * 4 + 1, (v.y + bb.y) * g);
                    atomicAdd(dst + j * 4 + 2, (v.z + bb.z) * g);
                    atomicAdd(dst + j * 4 + 3, (v.w + bb.w) * g);
                }
            }
        }
    }
}

// ---------------- aux loss ----------------
__global__ void aux_kernel(float* __restrict__ out, int out_size) {
    if (threadIdx.x == 0 && out_size > NTOK * DIMD) {
        float m = 0.f;
        for (int e = 0; e < NEXP; e++) m += g_importance[e];
        m /= (float)NEXP;
        float v = 0.f;
        for (int e = 0; e < NEXP; e++) { float d = g_importance[e] - m; v += d * d; }
        v /= (float)(NEXP - 1);
        float cv = sqrtf(v) / (m + 1e-8f);
        out[NTOK * DIMD] = cv * cv;
    }
}

// ---------------- launch ----------------
extern "C" void kernel_launch(void* const* d_in, const int* in_sizes, int n_in,
                              void* d_out, int out_size) {
    (void)in_sizes; (void)n_in;
    const float* x  = (const float*)d_in[0];
    const float* W1 = (const float*)d_in[1];
    const float* b1 = (const float*)d_in[2];
    const float* W2 = (const float*)d_in[3];
    const float* b2 = (const float*)d_in[4];
    const float* Wg = (const float*)d_in[5];
    const float* bg = (const float*)d_in[6];
    float* out = (float*)d_out;

    cudaFuncSetAttribute(moe_gemm<true>,  cudaFuncAttributeMaxDynamicSharedMemorySize, DYN_SMEM);
    cudaFuncSetAttribute(moe_gemm<false>, cudaFuncAttributeMaxDynamicSharedMemorySize, DYN_SMEM);

    init_kernel<<<256, 256>>>(out, x);
    prep_kernel<<<dim3(128, 128, 16), 256>>>(W1, W2);
    gate_kernel<<<NTOK, 128>>>(x, Wg, bg);
    plan_kernel<<<1, 32>>>();
    scatter_kernel<<<NTOK / 256, 256>>>();
    moe_gemm<true ><<<dim3(HID  / BN, MAXT), 256, DYN_SMEM>>>(b1, b2, out);
    moe_gemm<false><<<dim3(DIMD / BN, MAXT), 256, DYN_SMEM>>>(b1, b2, out);
    aux_kernel<<<1, 32>>>(out, out_size);
}

// round 8
// speedup vs baseline: 1.5359x; 1.5359x over previous
#include <cuda_runtime.h>
#include <cuda_fp16.h>
#include <cstdint>
#include <math.h>

// ---------------- problem dims ----------------
#define NTOK 8192
#define DIMD 1024
#define HID  4096
#define NEXP 8
#define NA   (NTOK*2)          // total assignments (top-2)

// ---------------- GEMM tiling ----------------
#define BM 128
#define BN 128
#define BKH 64                 // K per stage, in halves (128 bytes/row)
#define NS 3                   // cp.async pipeline stages
#define MAXT 144               // >= worst-case sum of ceil(cnt_e/128)
#define STAGEB (BM*BKH*2)      // 16 KB per operand tile (half)
#define STAGE_BYTES (2*STAGEB) // 32 KB per stage
#define DYN_SMEM (NS*STAGE_BYTES)   // 96 KB (also holds 128x132 f32 epilogue staging)
#define EPI_STRIDE 132

// ---------------- device scratch ----------------
__device__ __half g_xh [(size_t)NTOK*DIMD];        // fp16 x  [tok][D]
__device__ __half g_w1t[(size_t)NEXP*DIMD*HID];    // fp16 W1^T  [e][H][D]
__device__ __half g_w2t[(size_t)NEXP*HID*DIMD];    // fp16 W2^T  [e][D][H]
__device__ __half g_h  [(size_t)(NA+BM)*HID];      // fp16 hidden activations
__device__ int    g_top_idx[NTOK*2];
__device__ float  g_top_gate[NTOK*2];
__device__ int    g_count[NEXP];
__device__ int    g_offset[NEXP+1];
__device__ int    g_cursor[NEXP];
__device__ float  g_importance[NEXP];
__device__ int    g_tok[NA];
__device__ float  g_gate[NA];
__device__ int    g_tile_e[MAXT];
__device__ int    g_tile_m[MAXT];
__device__ int    g_ntiles;

// ---------------- PTX helpers ----------------
__device__ __forceinline__ uint32_t smem_u32(const void* p) {
    uint32_t a;
    asm("{ .reg .u64 t; cvta.to.shared.u64 t, %1; cvt.u32.u64 %0, t; }" : "=r"(a) : "l"(p));
    return a;
}
__device__ __forceinline__ void cpa16(uint32_t smem_dst, const void* gsrc) {
    asm volatile("cp.async.cg.shared.global [%0], [%1], 16;\n" :: "r"(smem_dst), "l"(gsrc));
}
#define CP_COMMIT() asm volatile("cp.async.commit_group;\n" ::: "memory")

__device__ __forceinline__ void ldsm4(uint32_t* r, uint32_t addr) {
    asm volatile("ldmatrix.sync.aligned.m8n8.x4.shared.b16 {%0,%1,%2,%3}, [%4];"
                 : "=r"(r[0]), "=r"(r[1]), "=r"(r[2]), "=r"(r[3]) : "r"(addr));
}
__device__ __forceinline__ void mma_f16(float* c, const uint32_t* a, const uint32_t* b) {
    asm volatile(
        "mma.sync.aligned.m16n8k16.row.col.f32.f16.f16.f32 "
        "{%0,%1,%2,%3}, {%4,%5,%6,%7}, {%8,%9}, {%0,%1,%2,%3};\n"
        : "+f"(c[0]), "+f"(c[1]), "+f"(c[2]), "+f"(c[3])
        : "r"(a[0]), "r"(a[1]), "r"(a[2]), "r"(a[3]), "r"(b[0]), "r"(b[1]));
}
// SW128 swizzle inside a [rows][128B] tile: 16B chunk index XOR low row bits
__device__ __forceinline__ uint32_t swz(uint32_t base, int row, int ch) {
    return base + (uint32_t)row * 128u + ((uint32_t)((ch ^ (row & 7)) & 7) << 4);
}

// ---------------- init: zero output + counters + x -> fp16 ----------------
__global__ void init_kernel(float* __restrict__ out, const float* __restrict__ x) {
    size_t i = (size_t)blockIdx.x * blockDim.x + threadIdx.x;
    size_t stride = (size_t)gridDim.x * blockDim.x;
    size_t n4 = (size_t)NTOK * DIMD / 4;
    float4 z = make_float4(0.f, 0.f, 0.f, 0.f);
    const float4* sx = (const float4*)x;
    __half2* dx = (__half2*)g_xh;
    for (size_t j = i; j < n4; j += stride) {
        reinterpret_cast<float4*>(out)[j] = z;
        float4 v = sx[j];
        dx[2*j]   = __floats2half2_rn(v.x, v.y);
        dx[2*j+1] = __floats2half2_rn(v.z, v.w);
    }
    if (blockIdx.x == 0 && threadIdx.x < NEXP) {
        g_count[threadIdx.x] = 0;
        g_importance[threadIdx.x] = 0.f;
    }
}

// ---------------- transpose + convert weights to fp16 ----------------
// z<8:  W1[e] [D][H] -> g_w1t[e] [H][D]
// z>=8: W2[e] [H][D] -> g_w2t[e] [D][H]
__global__ void prep_kernel(const float* __restrict__ W1, const float* __restrict__ W2) {
    const int z = blockIdx.z;
    const float* src; __half* dst; int R, C;
    if (z < NEXP) { src = W1 + (size_t)z*DIMD*HID;        dst = g_w1t + (size_t)z*DIMD*HID;        R = DIMD; C = HID; }
    else          { src = W2 + (size_t)(z-NEXP)*HID*DIMD; dst = g_w2t + (size_t)(z-NEXP)*HID*DIMD; R = HID;  C = DIMD; }
    const int j0 = blockIdx.x * 32, i0 = blockIdx.y * 32;
    if (j0 >= C || i0 >= R) return;
    __shared__ float t[32][33];
    const int tx = threadIdx.x & 31, ty = threadIdx.x >> 5;   // 256 threads: 32x8
#pragma unroll
    for (int k = 0; k < 4; k++)
        t[ty + k*8][tx] = src[(size_t)(i0 + ty + k*8) * C + j0 + tx];
    __syncthreads();
#pragma unroll
    for (int k = 0; k < 4; k++)
        dst[(size_t)(j0 + ty + k*8) * R + i0 + tx] = __float2half_rn(t[tx][ty + k*8]);
}

// ---------------- gating: one block per token ----------------
__global__ void gate_kernel(const float* __restrict__ x,
                            const float* __restrict__ Wg,
                            const float* __restrict__ bg) {
    const int t = blockIdx.x;
    const int tid = threadIdx.x;     // 128 threads
    const float* xr = x + (size_t)t * DIMD;

    float acc[NEXP];
#pragma unroll
    for (int e = 0; e < NEXP; e++) acc[e] = 0.f;
    for (int d = tid; d < DIMD; d += 128) {
        float xv = xr[d];
        const float* w = Wg + d * NEXP;
#pragma unroll
        for (int e = 0; e < NEXP; e++) acc[e] += xv * w[e];
    }
#pragma unroll
    for (int e = 0; e < NEXP; e++) {
#pragma unroll
        for (int o = 16; o > 0; o >>= 1)
            acc[e] += __shfl_down_sync(0xffffffffu, acc[e], o);
    }
    __shared__ float part[4][NEXP];
    if ((tid & 31) == 0) {
#pragma unroll
        for (int e = 0; e < NEXP; e++) part[tid >> 5][e] = acc[e];
    }
    __syncthreads();
    if (tid == 0) {
        float lg[NEXP];
#pragma unroll
        for (int e = 0; e < NEXP; e++)
            lg[e] = part[0][e] + part[1][e] + part[2][e] + part[3][e] + bg[e];
        float mx = lg[0];
        for (int e = 1; e < NEXP; e++) mx = fmaxf(mx, lg[e]);
        float s = 0.f, p[NEXP];
#pragma unroll
        for (int e = 0; e < NEXP; e++) { p[e] = expf(lg[e] - mx); s += p[e]; }
        float inv = 1.f / s;
#pragma unroll
        for (int e = 0; e < NEXP; e++) atomicAdd(&g_importance[e], p[e] * inv);
        int i1 = 0;
        for (int e = 1; e < NEXP; e++) if (lg[e] > lg[i1]) i1 = e;
        int i2 = -1;
        for (int e = 0; e < NEXP; e++)
            if (e != i1 && (i2 < 0 || lg[e] > lg[i2])) i2 = e;
        float e2 = expf(lg[i2] - lg[i1]);
        float g1 = 1.f / (1.f + e2);
        float g2 = e2 * g1;
        g_top_idx[2*t] = i1;  g_top_idx[2*t+1] = i2;
        g_top_gate[2*t] = g1; g_top_gate[2*t+1] = g2;
        atomicAdd(&g_count[i1], 1);
        atomicAdd(&g_count[i2], 1);
    }
}

// ---------------- plan + scatter ----------------
__global__ void plan_kernel() {
    if (threadIdx.x == 0 && blockIdx.x == 0) {
        int off = 0, nt = 0;
        for (int e = 0; e < NEXP; e++) {
            g_offset[e] = off;
            g_cursor[e] = 0;
            int c = g_count[e];
            off += c;
            int mt = (c + BM - 1) / BM;
            for (int i = 0; i < mt; i++) { g_tile_e[nt] = e; g_tile_m[nt] = i*BM; nt++; }
        }
        g_offset[NEXP] = off;
        g_ntiles = nt;
    }
}
__global__ void scatter_kernel() {
    int t = blockIdx.x * blockDim.x + threadIdx.x;
    if (t < NTOK) {
#pragma unroll
        for (int k = 0; k < 2; k++) {
            int e = g_top_idx[2*t+k];
            int p = atomicAdd(&g_cursor[e], 1);
            int s = g_offset[e] + p;
            g_tok[s] = t;
            g_gate[s] = g_top_gate[2*t+k];
        }
    }
}

// ---------------- grouped GEMM: fp16 mma.sync m16n8k16 + ldmatrix ----------------
// FIRST:  h = fp16(relu(gather(g_xh) @ W1[e] + b1[e]))   A:[128][1024]h  B^T:[H][D]h
// !FIRST: out[tok] += gate*(g_h @ W2[e] + b2[e])         A:[128][4096]h  B^T:[D][H]h
template<bool FIRST>
__global__ void __launch_bounds__(256, 1)
moe_gemm(const float* __restrict__ b1, const float* __restrict__ b2,
         float* __restrict__ out)
{
    const int tix = blockIdx.y;
    if (tix >= g_ntiles) return;
    const int e      = g_tile_e[tix];
    const int mstart = g_tile_m[tix];
    const int off    = g_offset[e];
    const int cnt    = g_count[e];
    const int n0     = blockIdx.x * BN;
    const int K      = FIRST ? DIMD : HID;   // in halves (elements)
    const int ldk    = FIRST ? DIMD : HID;   // B^T row length (k-contig)
    const int KIT    = K / BKH;
    const __half* Bt = FIRST ? (g_w1t + (size_t)e*DIMD*HID)
                             : (g_w2t + (size_t)e*HID*DIMD);

    extern __shared__ __align__(16) char dsm[];
    const uint32_t sbase = smem_u32(dsm);

    __shared__ int   s_tok[BM];
    __shared__ float s_gate[BM];

    const int tid  = threadIdx.x;
    const int wid  = tid >> 5, lane = tid & 31;
    const int wm   = wid >> 2, wn = wid & 3;      // 2x4 warp grid, warp tile 64m x 32n

    for (int r = tid; r < BM; r += 256) {
        int gr = mstart + r;
        bool v = gr < cnt;
        s_tok[r]  = v ? g_tok[off+gr]  : 0;
        s_gate[r] = v ? g_gate[off+gr] : 0.f;
    }
    __syncthreads();

    float acc[4][4][4];
#pragma unroll
    for (int i = 0; i < 4; i++)
#pragma unroll
        for (int j = 0; j < 4; j++)
#pragma unroll
            for (int q = 0; q < 4; q++) acc[i][j][q] = 0.f;

    // stage loader: A tile [128 rows][64 halves=128B] SW128, B tile [128 n][64 halves] SW128
    auto load_stage = [&](int buf, int k0) {
        uint32_t abuf = sbase + (uint32_t)buf * STAGE_BYTES;
        uint32_t bbuf = abuf + STAGEB;
#pragma unroll
        for (int i = 0; i < 4; i++) {
            int idx = tid + i * 256;          // 0..1023
            int row = idx >> 3, ch = idx & 7; // 16B chunk = 8 halves
            const __half* asrc;
            if (FIRST) asrc = g_xh + (size_t)s_tok[row] * DIMD + k0 + ch * 8;
            else       asrc = g_h  + (size_t)(off + mstart + row) * HID + k0 + ch * 8;
            cpa16(swz(abuf, row, ch), asrc);
        }
#pragma unroll
        for (int i = 0; i < 4; i++) {
            int idx = tid + i * 256;
            int row = idx >> 3, ch = idx & 7;   // row = n index
            cpa16(swz(bbuf, row, ch),
                  Bt + (size_t)(n0 + row) * ldk + k0 + ch * 8);
        }
    };

    load_stage(0, 0);       CP_COMMIT();
    load_stage(1, BKH);     CP_COMMIT();

    for (int kt = 0; kt < KIT; kt++) {
        const int buf = kt % NS;
        if (kt == KIT - 1) asm volatile("cp.async.wait_group 0;" ::: "memory");
        else               asm volatile("cp.async.wait_group 1;" ::: "memory");
        __syncthreads();

        if (kt + 2 < KIT) {                   // prefetch stage kt+2
            load_stage((kt + 2) % NS, (kt + 2) * BKH);
            CP_COMMIT();
        }

        const uint32_t abuf = sbase + (uint32_t)buf * STAGE_BYTES;
        const uint32_t bbuf = abuf + STAGEB;
#pragma unroll
        for (int ks = 0; ks < 4; ks++) {      // 4 x k16 per stage
            uint32_t a[4][4], b[2][4];
#pragma unroll
            for (int mi = 0; mi < 4; mi++) {
                // quads: {rows m0-7,ch 2ks} {m8-15,2ks} {m0-7,2ks+1} {m8-15,2ks+1}
                //      -> a0..a3 of m16n8k16 A fragment
                int row = wm * 64 + mi * 16 + (lane & 7) + ((lane >> 3) & 1) * 8;
                int ch  = ks * 2 + (lane >> 4);
                ldsm4(a[mi], swz(abuf, row, ch));
            }
#pragma unroll
            for (int nip = 0; nip < 2; nip++) {
                // quads: {n0-7,2ks} {n0-7,2ks+1} {n8-15,2ks} {n8-15,2ks+1}
                //      -> b0,b1 (low 8n), b0,b1 (high 8n)
                int row = wn * 32 + nip * 16 + (lane & 7) + ((lane >> 4) << 3);
                int ch  = ks * 2 + ((lane >> 3) & 1);
                ldsm4(b[nip], swz(bbuf, row, ch));
            }
#pragma unroll
            for (int mi = 0; mi < 4; mi++)
#pragma unroll
                for (int ni = 0; ni < 4; ni++)
                    mma_f16(acc[mi][ni], a[mi], &b[ni >> 1][(ni & 1) * 2]);
        }
        __syncthreads();
    }

    // ---- epilogue: stage accs to smem (stride 132), then coalesced flush ----
    float* st = (float*)dsm;
#pragma unroll
    for (int mi = 0; mi < 4; mi++) {
#pragma unroll
        for (int ni = 0; ni < 4; ni++) {
            int r = wm * 64 + mi * 16 + (lane >> 2);
            int c = wn * 32 + ni * 8 + ((lane & 3) << 1);
            *reinterpret_cast<float2*>(&st[r * EPI_STRIDE + c]) =
                make_float2(acc[mi][ni][0], acc[mi][ni][1]);
            *reinterpret_cast<float2*>(&st[(r + 8) * EPI_STRIDE + c]) =
                make_float2(acc[mi][ni][2], acc[mi][ni][3]);
        }
    }
    __syncthreads();

    {
        const int row  = tid >> 1;
        const int half_off = (tid & 1) * 64;
        if (mstart + row < cnt) {
            const float* bias = (FIRST ? b1 + (size_t)e * HID
                                       : b2 + (size_t)e * DIMD) + n0 + half_off;
            if (FIRST) {
                __half* dst = g_h + (size_t)(off + mstart + row) * HID + n0 + half_off;
#pragma unroll
                for (int j = 0; j < 16; j++) {
                    float4 v = *reinterpret_cast<float4*>(&st[row * EPI_STRIDE + half_off + j * 4]);
                    float4 bb = *reinterpret_cast<const float4*>(bias + j * 4);
                    __half2 p0 = __floats2half2_rn(fmaxf(v.x + bb.x, 0.f), fmaxf(v.y + bb.y, 0.f));
                    __half2 p1 = __floats2half2_rn(fmaxf(v.z + bb.z, 0.f), fmaxf(v.w + bb.w, 0.f));
                    *reinterpret_cast<__half2*>(dst + j * 4)     = p0;
                    *reinterpret_cast<__half2*>(dst + j * 4 + 2) = p1;
                }
            } else {
                const float g = s_gate[row];
                float* dst = out + (size_t)s_tok[row] * DIMD + n0 + half_off;
#pragma unroll
                for (int j = 0; j < 16; j++) {
                    float4 v = *reinterpret_cast<float4*>(&st[row * EPI_STRIDE + half_off + j * 4]);
                    float4 bb = *reinterpret_cast<const float4*>(bias + j * 4);
                    atomicAdd(dst + j * 4 + 0, (v.x + bb.x) * g);
                    atomicAdd(dst + j * 4 + 1, (v.y + bb.y) * g);
                    atomicAdd(dst + j * 4 + 2, (v.z + bb.z) * g);
                    atomicAdd(dst + j * 4 + 3, (v.w + bb.w) * g);
                }
            }
        }
    }
}

// ---------------- aux loss ----------------
__global__ void aux_kernel(float* __restrict__ out, int out_size) {
    if (threadIdx.x == 0 && out_size > NTOK * DIMD) {
        float m = 0.f;
        for (int e = 0; e < NEXP; e++) m += g_importance[e];
        m /= (float)NEXP;
        float v = 0.f;
        for (int e = 0; e < NEXP; e++) { float d = g_importance[e] - m; v += d * d; }
        v /= (float)(NEXP - 1);
        float cv = sqrtf(v) / (m + 1e-8f);
        out[NTOK * DIMD] = cv * cv;
    }
}

// ---------------- launch ----------------
extern "C" void kernel_launch(void* const* d_in, const int* in_sizes, int n_in,
                              void* d_out, int out_size) {
    (void)in_sizes; (void)n_in;
    const float* x  = (const float*)d_in[0];
    const float* W1 = (const float*)d_in[1];
    const float* b1 = (const float*)d_in[2];
    const float* W2 = (const float*)d_in[3];
    const float* b2 = (const float*)d_in[4];
    const float* Wg = (const float*)d_in[5];
    const float* bg = (const float*)d_in[6];
    float* out = (float*)d_out;

    cudaFuncSetAttribute(moe_gemm<true>,  cudaFuncAttributeMaxDynamicSharedMemorySize, DYN_SMEM);
    cudaFuncSetAttribute(moe_gemm<false>, cudaFuncAttributeMaxDynamicSharedMemorySize, DYN_SMEM);

    init_kernel<<<256, 256>>>(out, x);
    prep_kernel<<<dim3(128, 128, 16), 256>>>(W1, W2);
    gate_kernel<<<NTOK, 128>>>(x, Wg, bg);
    plan_kernel<<<1, 32>>>();
    scatter_kernel<<<NTOK / 256, 256>>>();
    moe_gemm<true ><<<dim3(HID  / BN, MAXT), 256, DYN_SMEM>>>(b1, b2, out);
    moe_gemm<false><<<dim3(DIMD / BN, MAXT), 256, DYN_SMEM>>>(b1, b2, out);
    aux_kernel<<<1, 32>>>(out, out_size);
}